// round 14
// baseline (speedup 1.0000x reference)
#include <cuda_runtime.h>
#include <cuda_fp16.h>
#include <cstdint>
#include <math.h>

#define NCAM 4
#define FCH 256
#define IH 45
#define IW 80
#define HWPX (IH*IW)            // 3600
#define NPX (NCAM*HWPX)         // 14400
#define DD 99
#define CC 128
#define NXV 100
#define NYV 100
#define NZV 5
#define NXY (NXV*NYV)

#define TILES_PER_CAM 29        // ceil(3600/128)
#define NTILES (TILES_PER_CAM*NCAM)
#define KCH 4                   // 256/64 A-chunks per tap (pure fp16)

// ---------------- scratch ----------------
__device__ __half g_actA[(size_t)NPX*256];   // [px][256] fp16
__device__ __half g_actB[(size_t)NPX*256];
__device__ __half g_wp1[9*4*256*64];
__device__ __half g_wp2[9*4*256*64];
__device__ __half g_wp3[4*256*64];
__device__ float g_logits[(size_t)NPX*256];  // [px][227 used]
__device__ float g_ss[1280];
__device__ float g_mats[NCAM][24];
__device__ __align__(16) float g_scratch[(size_t)NZV*NXY*CC];  // [vz][xy][c]

// ---------------- helpers ----------------
__device__ __forceinline__ uint32_t smem_to_u32(const void* p) {
    uint32_t a;
    asm("{ .reg .u64 t; cvta.to.shared.u64 t, %1; cvt.u32.u64 %0, t; }" : "=r"(a) : "l"(p));
    return a;
}
__device__ __forceinline__ void cp_async16(uint32_t dst, const void* src, int sz) {
    asm volatile("cp.async.cg.shared.global [%0], [%1], 16, %2;"
                 :: "r"(dst), "l"(src), "r"(sz) : "memory");
}
__device__ __forceinline__ void cp_commit() { asm volatile("cp.async.commit_group;" ::: "memory"); }
__device__ __forceinline__ void cp_wait1()  { asm volatile("cp.async.wait_group 1;" ::: "memory"); }
__device__ __forceinline__ void cp_wait0()  { asm volatile("cp.async.wait_group 0;" ::: "memory"); }

__device__ __forceinline__ void ldmx4(uint32_t addr, uint32_t& r0, uint32_t& r1, uint32_t& r2, uint32_t& r3) {
    asm volatile("ldmatrix.sync.aligned.m8n8.x4.shared.b16 {%0,%1,%2,%3}, [%4];"
                 : "=r"(r0), "=r"(r1), "=r"(r2), "=r"(r3) : "r"(addr));
}
__device__ __forceinline__ void mma16816(float* d, const uint32_t* a, uint32_t b0, uint32_t b1) {
    asm volatile("mma.sync.aligned.m16n8k16.row.col.f32.f16.f16.f32 "
                 "{%0,%1,%2,%3}, {%4,%5,%6,%7}, {%8,%9}, {%0,%1,%2,%3};"
                 : "+f"(d[0]), "+f"(d[1]), "+f"(d[2]), "+f"(d[3])
                 : "r"(a[0]), "r"(a[1]), "r"(a[2]), "r"(a[3]), "r"(b0), "r"(b1));
}

// ---------------- smem layout: 128px x 256co tile, 3-stage ----------------
#define RSTRIDE 144
#define OFF_SS   0
#define OFF_A0   2048
#define A_BYTES  (128*RSTRIDE)          // 18432
#define B_BYTES  (256*RSTRIDE)          // 36864
#define STAGE_BYTES (A_BYTES + B_BYTES) // 55296
#define SMEM_TOTAL (OFF_A0 + 3*STAGE_BYTES)  // 167936

// ---------------- GEMM conv kernel (mma.sync fp16, fp32 accum) ----------------
__global__ __launch_bounds__(512, 1)
void gemm_conv(const __half* __restrict__ act_in,
               const __half* __restrict__ wp,
               const float* __restrict__ ssA, const float* __restrict__ ssB,
               __half* __restrict__ act_out,
               float* __restrict__ logits_out,
               int taps, int mode)
{
    extern __shared__ char smem[];
    uint32_t smem_base = smem_to_u32(smem);
    int tid = threadIdx.x;
    int wid = tid >> 5;
    int lane = tid & 31;

    int tile = blockIdx.x;
    int cam = tile / TILES_PER_CAM;
    int p0  = (tile % TILES_PER_CAM) * 128;

    {
        float* s_ss = (float*)smem;
        if (tid < 256) s_ss[tid] = ssA[tid];
        else           s_ss[tid] = ssB ? ssB[tid - 256] : 0.f;
    }

    const __half* abase = act_in + (size_t)cam * HWPX * 256;
    int nch = taps * KCH;

    int warp_m = wid >> 2, warp_n = wid & 3;
    int m0 = warp_m * 32;
    int n0 = warp_n * 64;

    float acc[2][8][4];
    #pragma unroll
    for (int a = 0; a < 2; a++)
        #pragma unroll
        for (int b = 0; b < 8; b++)
            #pragma unroll
            for (int c = 0; c < 4; c++) acc[a][b][c] = 0.f;

    int aseg = tid & 7;
    int arr  = tid >> 3;                // 0..63
    int ap0  = p0 + arr, ap1 = ap0 + 64;
    int ah0  = ap0 / IW, aw0 = ap0 % IW;
    int ah1  = ap1 / IW, aw1 = ap1 % IW;

    auto load_chunk = [&](int k, int stage) {
        uint32_t sa = smem_base + OFF_A0 + stage * STAGE_BYTES;
        uint32_t sb = sa + A_BYTES;
        int tap = k / KCH, kc = k % KCH;
        int dy = (taps == 9) ? (tap / 3 - 1) : 0;
        int dx = (taps == 9) ? (tap % 3 - 1) : 0;
        int cbase = kc * 64;
        {
            int h2 = ah0 + dy, w2 = aw0 + dx;
            bool ok = (ap0 < HWPX) && (h2 >= 0) && (h2 < IH) && (w2 >= 0) && (w2 < IW);
            const __half* gp = ok
                ? (abase + (size_t)(h2 * IW + w2) * 256 + cbase + aseg * 8)
                : abase;
            cp_async16(sa + arr * RSTRIDE + aseg * 16, gp, ok ? 16 : 0);
        }
        {
            int h2 = ah1 + dy, w2 = aw1 + dx;
            bool ok = (ap1 < HWPX) && (h2 >= 0) && (h2 < IH) && (w2 >= 0) && (w2 < IW);
            const __half* gp = ok
                ? (abase + (size_t)(h2 * IW + w2) * 256 + cbase + aseg * 8)
                : abase;
            cp_async16(sa + (arr + 64) * RSTRIDE + aseg * 16, gp, ok ? 16 : 0);
        }
        const __half* wb = wp + (size_t)k * (256 * 64);
        #pragma unroll
        for (int i = 0; i < 4; i++) {
            int idx = tid + i * 512;
            int r = idx >> 3, seg = idx & 7;
            cp_async16(sb + r * RSTRIDE + seg * 16, wb + r * 64 + seg * 8, 16);
        }
        cp_commit();
    };

    load_chunk(0, 0);
    if (nch > 1) load_chunk(1, 1);

    for (int k = 0; k < nch; k++) {
        if (k + 1 < nch) cp_wait1(); else cp_wait0();
        __syncthreads();
        if (k + 2 < nch) load_chunk(k + 2, (k + 2) % 3);

        uint32_t sa = smem_base + OFF_A0 + (k % 3) * STAGE_BYTES;
        uint32_t sb = sa + A_BYTES;
        uint32_t a_row = m0 + (lane & 15);
        uint32_t a_coloff = (lane >> 4) * 16;
        uint32_t b_row = n0 + (lane >> 4) * 8 + (lane & 7);
        uint32_t b_coloff = ((lane >> 3) & 1) * 16;

        #pragma unroll
        for (int kk = 0; kk < 4; kk++) {
            uint32_t af[2][4];
            #pragma unroll
            for (int mf = 0; mf < 2; mf++) {
                uint32_t addr = sa + (a_row + mf * 16) * RSTRIDE + kk * 32 + a_coloff;
                ldmx4(addr, af[mf][0], af[mf][1], af[mf][2], af[mf][3]);
            }
            uint32_t bf[4][4];
            #pragma unroll
            for (int nf2 = 0; nf2 < 4; nf2++) {
                uint32_t addr = sb + (b_row + nf2 * 16) * RSTRIDE + kk * 32 + b_coloff;
                ldmx4(addr, bf[nf2][0], bf[nf2][1], bf[nf2][2], bf[nf2][3]);
            }
            #pragma unroll
            for (int mf = 0; mf < 2; mf++)
                #pragma unroll
                for (int nf = 0; nf < 8; nf++)
                    mma16816(acc[mf][nf], af[mf], bf[nf >> 1][(nf & 1) * 2], bf[nf >> 1][(nf & 1) * 2 + 1]);
        }
    }

    const float* s_ss = (const float*)smem;
    int trow = lane >> 2;
    int tc   = (lane & 3) * 2;

    #pragma unroll
    for (int mf = 0; mf < 2; mf++) {
        #pragma unroll
        for (int hf = 0; hf < 2; hf++) {
            int pr = m0 + mf * 16 + hf * 8 + trow;
            int p = p0 + pr;
            if (p >= HWPX) continue;
            size_t pxg = (size_t)cam * HWPX + p;
            #pragma unroll
            for (int nf = 0; nf < 8; nf++) {
                int co = n0 + nf * 8 + tc;
                float d0 = acc[mf][nf][hf * 2];
                float d1 = acc[mf][nf][hf * 2 + 1];
                if (mode == 0) {
                    float y0 = fmaxf(d0 * s_ss[co]     + s_ss[256 + co],     0.f);
                    float y1 = fmaxf(d1 * s_ss[co + 1] + s_ss[256 + co + 1], 0.f);
                    *(__half2*)(act_out + pxg * 256 + co) =
                        __halves2half2(__float2half_rn(y0), __float2half_rn(y1));
                } else {
                    float2 v = make_float2(d0 + s_ss[co], d1 + s_ss[co + 1]);
                    *(float2*)(logits_out + pxg * 256 + co) = v;
                }
            }
        }
    }
}

// ---------------- fused mega-prep: weights | convert | small | scratch-zero ----------------
#define W3X3_ELEMS (9*4*256*64)
#define W1X1_ELEMS (4*256*64)
#define WTOTAL     (2*W3X3_ELEMS + W1X1_ELEMS)
#define WBLOCKS    (WTOTAL/256)
#define CVX        ((HWPX+63)/64)
#define CVBLOCKS   (CVX*4*NCAM)
#define ZTOTAL     (NZV*NXY*CC)
#define ZPERBLK    (256*16)
#define ZBLOCKS    ((ZTOTAL+ZPERBLK-1)/ZPERBLK)
#define MEGA_BLOCKS (WBLOCKS + CVBLOCKS + 1 + ZBLOCKS)

__device__ void inv3(const float* a, float* o) {
    float det = a[0]*(a[4]*a[8]-a[5]*a[7]) - a[1]*(a[3]*a[8]-a[5]*a[6]) + a[2]*(a[3]*a[7]-a[4]*a[6]);
    float id = 1.0f/det;
    o[0]=(a[4]*a[8]-a[5]*a[7])*id; o[1]=(a[2]*a[7]-a[1]*a[8])*id; o[2]=(a[1]*a[5]-a[2]*a[4])*id;
    o[3]=(a[5]*a[6]-a[3]*a[8])*id; o[4]=(a[0]*a[8]-a[2]*a[6])*id; o[5]=(a[2]*a[3]-a[0]*a[5])*id;
    o[6]=(a[3]*a[7]-a[4]*a[6])*id; o[7]=(a[1]*a[6]-a[0]*a[7])*id; o[8]=(a[0]*a[4]-a[1]*a[3])*id;
}

__global__ __launch_bounds__(256)
void mega_prep(const float* __restrict__ w1, const float* __restrict__ w2,
               const float* __restrict__ w3,
               __half* __restrict__ wp1, __half* __restrict__ wp2, __half* __restrict__ wp3,
               const float* __restrict__ img, __half* __restrict__ actA,
               const float* b1, const float* g1, const float* be1, const float* m1, const float* v1,
               const float* b2, const float* g2, const float* be2, const float* m2, const float* v2,
               const float* b3,
               const float* rot, const float* ctrans, const float* intr,
               const float* prot, const float* ptrans,
               float* __restrict__ scratch)
{
    __shared__ float s[64][65];
    int bx = blockIdx.x;
    int tid = threadIdx.x;

    if (bx < WBLOCKS) {
        int idx = bx * 256 + tid;
        if (idx < 2 * W3X3_ELEMS) {
            const float* w = (idx < W3X3_ELEMS) ? w1 : w2;
            __half* wp = (idx < W3X3_ELEMS) ? wp1 : wp2;
            int e = (idx < W3X3_ELEMS) ? idx : idx - W3X3_ELEMS;
            int j   = e & 63;
            int co  = (e >> 6) & 255;
            int kc  = (e >> 14) & 3;
            int tap = e >> 16;
            int ci = kc * 64 + j;
            int ky = tap / 3, kx = tap % 3;
            wp[e] = __float2half_rn(w[(((size_t)co * 256 + ci) * 3 + ky) * 3 + kx]);
        } else {
            int e = idx - 2 * W3X3_ELEMS;
            int j  = e & 63;
            int co = (e >> 6) & 255;
            int kc = e >> 14;
            int ci = kc * 64 + j;
            float v = (co < 227) ? w3[(size_t)co * 256 + ci] : 0.f;
            wp3[e] = __float2half_rn(v);
        }
        return;
    }
    bx -= WBLOCKS;

    if (bx < CVBLOCKS) {
        int x = bx % CVX;
        int y = (bx / CVX) & 3;
        int n = bx / (CVX * 4);
        int ci0 = y * 64;
        int p0 = x * 64;
        for (int idx = tid; idx < 64 * 64; idx += 256) {
            int ci = idx / 64, p = idx % 64;
            float v = 0.f;
            if (p0 + p < HWPX) v = img[((size_t)(n * FCH + ci0 + ci)) * HWPX + p0 + p];
            s[ci][p] = v;
        }
        __syncthreads();
        for (int idx = tid; idx < 64 * 64; idx += 256) {
            int p = idx / 64, ci = idx % 64;
            if (p0 + p >= HWPX) continue;
            actA[((size_t)n * HWPX + p0 + p) * 256 + ci0 + ci] = __float2half_rn(s[ci][p]);
        }
        return;
    }
    bx -= CVBLOCKS;

    if (bx == 0) {
        int c = tid;
        float s1 = g1[c] * rsqrtf(v1[c] + 1e-3f);
        g_ss[c] = s1;
        g_ss[256 + c] = be1[c] + (b1[c] - m1[c]) * s1;
        float s2 = g2[c] * rsqrtf(v2[c] + 1e-3f);
        g_ss[512 + c] = s2;
        g_ss[768 + c] = be2[c] + (b2[c] - m2[c]) * s2;
        g_ss[1024 + c] = (c < 227) ? b3[c] : 0.f;
        if (c < NCAM) {
            int n = c;
            float invK[9], invPR[9];
            inv3(intr + n*9, invK);
            inv3(prot + n*9, invPR);
            const float* R = rot + n*9;
            float* m = g_mats[n];
            #pragma unroll
            for (int i=0;i<3;i++)
                #pragma unroll
                for (int j=0;j<3;j++){
                    float acc2=0.f;
                    #pragma unroll
                    for (int k2=0;k2<3;k2++) acc2 += R[i*3+k2]*invK[k2*3+j];
                    m[i*3+j]=acc2;
                }
            #pragma unroll
            for (int i=0;i<9;i++) m[9+i]=invPR[i];
            #pragma unroll
            for (int i=0;i<3;i++){ m[18+i]=ptrans[n*3+i]; m[21+i]=ctrans[n*3+i]; }
        }
        return;
    }
    bx -= 1;

    {
        size_t base = (size_t)bx * ZPERBLK + (size_t)tid * 16;
        float4 z = make_float4(0.f, 0.f, 0.f, 0.f);
        #pragma unroll
        for (int i = 0; i < 4; i++) {
            size_t off = base + i * 4;
            if (off < ZTOTAL) *(float4*)(scratch + off) = z;
        }
    }
}

// ---------------- fused softmax + geometry + 8-ray-merged scatter ----------------
// Block = 8 rays (same h, consecutive w). 256 threads = 8 warps, one ray/warp.
// Dynamic smem layout (bytes):
#define RAYS 8
#define MAXE8 (RAYS*DD)                 // 792
#define SC_M    0                        // 24 f
#define SC_P    96                       // 8*99 f  -> 3168
#define SC_VOX  3264                     // 8*99 i  -> 3168
#define SC_CTX  6432                     // 8*128 f -> 4096 (16-aligned)
#define SC_EVOX 10528                    // 792 i
#define SC_ERAY 13696                    // 792 i
#define SC_EW   16864                    // 792 f
#define SC_LW   20032                    // 792*8 f -> 25344
#define SC_LEAD 45376                    // 792 i
#define SC_N    48544                    // 1 i
#define SC_TOTAL 48640

__global__ __launch_bounds__(256)
void scatter_kernel(const float* __restrict__ logits, float* __restrict__ scratch)
{
    extern __shared__ char sm[];
    float* s_m    = (float*)(sm + SC_M);
    float* s_p    = (float*)(sm + SC_P);
    int*   s_vox  = (int*)  (sm + SC_VOX);
    float* s_ctx  = (float*)(sm + SC_CTX);
    int*   s_evox = (int*)  (sm + SC_EVOX);
    int*   s_eray = (int*)  (sm + SC_ERAY);
    float* s_ew   = (float*)(sm + SC_EW);
    float* s_lw   = (float*)(sm + SC_LW);
    int*   s_lead = (int*)  (sm + SC_LEAD);
    int*   s_n    = (int*)  (sm + SC_N);

    int blk = blockIdx.x;
    int n   = blk / (HWPX/RAYS);
    int q   = blk % (HWPX/RAYS);
    int h   = q / (IW/RAYS);
    int w0  = (q % (IW/RAYS)) * RAYS;
    int t = threadIdx.x, lane = t & 31, warp = t >> 5;   // warp 0..7 = ray

    if (t < 24) s_m[t] = g_mats[n][t];
    if (t == 0) *s_n = 0;
    const float* lgbase = logits + ((size_t)n * HWPX + h * IW + w0) * 256;
    for (int i = t; i < RAYS * CC; i += 256) {
        int r = i >> 7, c = i & 127;
        s_ctx[i] = lgbase[r * 256 + DD + c];
    }
    __syncthreads();

    // ---- per-warp: softmax + geometry + run extraction for ray `warp` ----
    {
        int r = warp;
        const float* lg = lgbase + r * 256;
        float xv[4];
        float lmax = -1e30f;
        #pragma unroll
        for (int j = 0; j < 4; j++) {
            int d = lane + 32 * j;
            xv[j] = (d < DD) ? lg[d] : -1e30f;
            lmax = fmaxf(lmax, xv[j]);
        }
        #pragma unroll
        for (int o = 16; o; o >>= 1) lmax = fmaxf(lmax, __shfl_xor_sync(0xffffffffu, lmax, o));
        float ev[4], lsum = 0.f;
        #pragma unroll
        for (int j = 0; j < 4; j++) {
            int d = lane + 32 * j;
            ev[j] = (d < DD) ? __expf(xv[j] - lmax) : 0.f;
            lsum += ev[j];
        }
        #pragma unroll
        for (int o = 16; o; o >>= 1) lsum += __shfl_xor_sync(0xffffffffu, lsum, o);
        float inv = 1.f / lsum;

        float fx = (w0 + r) * (639.0f / 79.0f);
        float fy = h * (359.0f / 44.0f);
        #pragma unroll
        for (int j = 0; j < 4; j++) {
            int d = lane + 32 * j;
            if (d >= DD) continue;
            s_p[r * DD + d] = ev[j] * inv;
            float dv = (float)(d + 1);
            float q0 = fx - s_m[18], q1 = fy - s_m[19], q2 = dv - s_m[20];
            float r0 = s_m[ 9]*q0 + s_m[10]*q1 + s_m[11]*q2;
            float r1 = s_m[12]*q0 + s_m[13]*q1 + s_m[14]*q2;
            float r2 = s_m[15]*q0 + s_m[16]*q1 + s_m[17]*q2;
            float t0 = r0*r2, t1 = r1*r2, t2 = r2;
            float gx = s_m[0]*t0 + s_m[1]*t1 + s_m[2]*t2 + s_m[21];
            float gy = s_m[3]*t0 + s_m[4]*t1 + s_m[5]*t2 + s_m[22];
            float gz = s_m[6]*t0 + s_m[7]*t1 + s_m[8]*t2 + s_m[23];
            int vx = (int)floorf(gx * 0.5f);
            int vy = (int)floorf((gy + 100.f) * 0.5f);
            int vz = (int)floorf((gz + 10.f) * 0.25f);
            bool kept = (vx>=0 && vx<NXV && vy>=0 && vy<NYV && vz>=0 && vz<NZV);
            s_vox[r * DD + d] = kept ? (vz*NXY + vx*NYV + vy) : -1;
        }
        __syncwarp();
        #pragma unroll
        for (int j = 0; j < 4; j++) {
            int d = lane + 32 * j;
            if (d >= DD) continue;
            int v = s_vox[r * DD + d];
            if (v < 0) continue;
            bool f = (d == 0) || (s_vox[r * DD + d - 1] != v);
            if (!f) continue;
            float wsum = s_p[r * DD + d];
            int dd = d + 1;
            while (dd < DD && s_vox[r * DD + dd] == v) { wsum += s_p[r * DD + dd]; dd++; }
            int idx = atomicAdd(s_n, 1);
            s_evox[idx] = v;
            s_eray[idx] = r;
            s_ew[idx]   = wsum;
        }
    }
    __syncthreads();

    int N = *s_n;
    for (int i = t; i < N * RAYS; i += 256) s_lw[i] = 0.f;
    __syncthreads();

    // ---- first-occurrence dedup across all 8 rays ----
    for (int i = t; i < N; i += 256) {
        int v = s_evox[i];
        int first = i;
        for (int j = 0; j < i; j++)
            if (s_evox[j] == v) { first = j; break; }
        s_lead[i] = (first == i) ? 1 : 0;
        atomicAdd(&s_lw[first * RAYS + s_eray[i]], s_ew[i]);
    }
    __syncthreads();

    // ---- flush distinct voxels: combine 8 rays per red.v4 ----
    float4 cv[RAYS];
    #pragma unroll
    for (int r = 0; r < RAYS; r++)
        cv[r] = ((const float4*)(s_ctx + r * CC))[lane];
    for (int e = warp; e < N; e += RAYS) {
        if (!s_lead[e]) continue;
        float vx = 0.f, vy = 0.f, vz = 0.f, vw = 0.f;
        #pragma unroll
        for (int r = 0; r < RAYS; r++) {
            float a = s_lw[e * RAYS + r];
            vx += a * cv[r].x; vy += a * cv[r].y;
            vz += a * cv[r].z; vw += a * cv[r].w;
        }
        float* ptr = scratch + (size_t)s_evox[e] * CC + lane * 4;
        asm volatile("red.global.add.v4.f32 [%0], {%1,%2,%3,%4};"
                     :: "l"(ptr), "f"(vx), "f"(vy), "f"(vz), "f"(vw)
                     : "memory");
    }
}

// ---------------- scratch [vz][xy][c] -> out [vz][c][xy] ----------------
__global__ __launch_bounds__(256)
void bev_transpose(const float* __restrict__ scratch, float* __restrict__ out)
{
    __shared__ float s[32][129];
    int vz = blockIdx.y;
    int xy0 = blockIdx.x * 32;
    int tid = threadIdx.x;
    #pragma unroll
    for (int i = 0; i < 16; i++) {
        int idx = tid + i * 256;
        int c = idx & 127, xyl = idx >> 7;
        int xy = xy0 + xyl;
        s[xyl][c] = (xy < NXY) ? scratch[((size_t)vz * NXY + xy) * CC + c] : 0.f;
    }
    __syncthreads();
    #pragma unroll
    for (int i = 0; i < 16; i++) {
        int idx = tid + i * 256;
        int xyl = idx & 31, c = idx >> 5;
        int xy = xy0 + xyl;
        if (xy < NXY) out[((size_t)vz * CC + c) * NXY + xy] = s[xyl][c];
    }
}

// ---------------- launcher ----------------
extern "C" void kernel_launch(void* const* d_in, const int* in_sizes, int n_in,
                              void* d_out, int out_size)
{
    const float* rot    = (const float*)d_in[0];
    const float* ctrans = (const float*)d_in[1];
    const float* intr   = (const float*)d_in[2];
    const float* prot   = (const float*)d_in[3];
    const float* ptrans = (const float*)d_in[4];
    const float* img    = (const float*)d_in[5];
    const float* w1 = (const float*)d_in[6];
    const float* b1 = (const float*)d_in[7];
    const float* g1 = (const float*)d_in[8];
    const float* be1= (const float*)d_in[9];
    const float* m1 = (const float*)d_in[10];
    const float* v1 = (const float*)d_in[11];
    const float* w2 = (const float*)d_in[12];
    const float* b2 = (const float*)d_in[13];
    const float* g2 = (const float*)d_in[14];
    const float* be2= (const float*)d_in[15];
    const float* m2 = (const float*)d_in[16];
    const float* v2 = (const float*)d_in[17];
    const float* w3 = (const float*)d_in[18];
    const float* b3 = (const float*)d_in[19];
    float* out = (float*)d_out;

    __half *actA, *actB, *wp1, *wp2, *wp3;
    float *logits, *ss, *scratch;
    cudaGetSymbolAddress((void**)&actA, g_actA);
    cudaGetSymbolAddress((void**)&actB, g_actB);
    cudaGetSymbolAddress((void**)&wp1, g_wp1);
    cudaGetSymbolAddress((void**)&wp2, g_wp2);
    cudaGetSymbolAddress((void**)&wp3, g_wp3);
    cudaGetSymbolAddress((void**)&logits, g_logits);
    cudaGetSymbolAddress((void**)&ss, g_ss);
    cudaGetSymbolAddress((void**)&scratch, g_scratch);

    cudaFuncSetAttribute(gemm_conv, cudaFuncAttributeMaxDynamicSharedMemorySize, SMEM_TOTAL);
    cudaFuncSetAttribute(scatter_kernel, cudaFuncAttributeMaxDynamicSharedMemorySize, SC_TOTAL);

    mega_prep<<<MEGA_BLOCKS, 256>>>(w1, w2, w3, wp1, wp2, wp3,
                                    img, actA,
                                    b1,g1,be1,m1,v1, b2,g2,be2,m2,v2, b3,
                                    rot, ctrans, intr, prot, ptrans,
                                    scratch);

    gemm_conv<<<NTILES, 512, SMEM_TOTAL>>>(actA, wp1, ss,        ss + 256, actB, nullptr, 9, 0);
    gemm_conv<<<NTILES, 512, SMEM_TOTAL>>>(actB, wp2, ss + 512,  ss + 768, actA, nullptr, 9, 0);
    gemm_conv<<<NTILES, 512, SMEM_TOTAL>>>(actA, wp3, ss + 1024, nullptr,  nullptr, logits, 1, 1);

    scatter_kernel<<<NPX/RAYS, 256, SC_TOTAL>>>(logits, scratch);

    bev_transpose<<<dim3((NXY + 31)/32, NZV), 256>>>(scratch, out);
}

// round 15
// speedup vs baseline: 1.2075x; 1.2075x over previous
#include <cuda_runtime.h>
#include <cuda_fp16.h>
#include <cstdint>
#include <math.h>

#define NCAM 4
#define FCH 256
#define IH 45
#define IW 80
#define HWPX (IH*IW)            // 3600
#define NPX (NCAM*HWPX)         // 14400
#define DD 99
#define CC 128
#define NXV 100
#define NYV 100
#define NZV 5
#define NXY (NXV*NYV)

#define TILES_PER_CAM 29        // ceil(3600/128)
#define NTILES (TILES_PER_CAM*NCAM)
#define KCH 4                   // 256/64 A-chunks per tap (pure fp16)

// ---------------- scratch ----------------
__device__ __half g_actA[(size_t)NPX*256];   // [px][256] fp16
__device__ __half g_actB[(size_t)NPX*256];
__device__ __half g_wp1[9*4*256*64];
__device__ __half g_wp2[9*4*256*64];
__device__ __half g_wp3[4*256*64];
__device__ float g_logits[(size_t)NPX*256];  // [px][227 used]
__device__ float g_ss[1280];
__device__ float g_mats[NCAM][24];
__device__ __align__(16) float g_scratch[(size_t)NZV*NXY*CC];  // [vz][xy][c]

// ---------------- helpers ----------------
__device__ __forceinline__ uint32_t smem_to_u32(const void* p) {
    uint32_t a;
    asm("{ .reg .u64 t; cvta.to.shared.u64 t, %1; cvt.u32.u64 %0, t; }" : "=r"(a) : "l"(p));
    return a;
}
__device__ __forceinline__ void cp_async16(uint32_t dst, const void* src, int sz) {
    asm volatile("cp.async.cg.shared.global [%0], [%1], 16, %2;"
                 :: "r"(dst), "l"(src), "r"(sz) : "memory");
}
__device__ __forceinline__ void cp_commit() { asm volatile("cp.async.commit_group;" ::: "memory"); }
__device__ __forceinline__ void cp_wait0()  { asm volatile("cp.async.wait_group 0;" ::: "memory"); }

__device__ __forceinline__ void ldmx4(uint32_t addr, uint32_t& r0, uint32_t& r1, uint32_t& r2, uint32_t& r3) {
    asm volatile("ldmatrix.sync.aligned.m8n8.x4.shared.b16 {%0,%1,%2,%3}, [%4];"
                 : "=r"(r0), "=r"(r1), "=r"(r2), "=r"(r3) : "r"(addr));
}
__device__ __forceinline__ void mma16816(float* d, const uint32_t* a, uint32_t b0, uint32_t b1) {
    asm volatile("mma.sync.aligned.m16n8k16.row.col.f32.f16.f16.f32 "
                 "{%0,%1,%2,%3}, {%4,%5,%6,%7}, {%8,%9}, {%0,%1,%2,%3};"
                 : "+f"(d[0]), "+f"(d[1]), "+f"(d[2]), "+f"(d[3])
                 : "r"(a[0]), "r"(a[1]), "r"(a[2]), "r"(a[3]), "r"(b0), "r"(b1));
}

// ---------------- smem layout: 128px x 256co tile, 4-stage ----------------
#define RSTRIDE 144
#define OFF_SS   0
#define OFF_A0   2048
#define A_BYTES  (128*RSTRIDE)          // 18432
#define B_BYTES  (256*RSTRIDE)          // 36864
#define STAGE_BYTES (A_BYTES + B_BYTES) // 55296
#define SMEM_TOTAL (OFF_A0 + 4*STAGE_BYTES)  // 223232

// ---------------- GEMM conv kernel (mma.sync fp16, fp32 accum) ----------------
// Block: 512 threads = 16 warps (4m x 4n). Tile 128 px x 256 co.
// 4-stage cp.async pipeline, 2 chunks per __syncthreads.
__global__ __launch_bounds__(512, 1)
void gemm_conv(const __half* __restrict__ act_in,
               const __half* __restrict__ wp,
               const float* __restrict__ ssA, const float* __restrict__ ssB,
               __half* __restrict__ act_out,
               float* __restrict__ logits_out,
               int taps, int mode)
{
    extern __shared__ char smem[];
    uint32_t smem_base = smem_to_u32(smem);
    int tid = threadIdx.x;
    int wid = tid >> 5;
    int lane = tid & 31;

    int tile = blockIdx.x;
    int cam = tile / TILES_PER_CAM;
    int p0  = (tile % TILES_PER_CAM) * 128;

    {
        float* s_ss = (float*)smem;
        if (tid < 256) s_ss[tid] = ssA[tid];
        else           s_ss[tid] = ssB ? ssB[tid - 256] : 0.f;
    }

    const __half* abase = act_in + (size_t)cam * HWPX * 256;
    int nch = taps * KCH;     // 36 or 4 (always even)

    int warp_m = wid >> 2, warp_n = wid & 3;
    int m0 = warp_m * 32;
    int n0 = warp_n * 64;

    float acc[2][8][4];
    #pragma unroll
    for (int a = 0; a < 2; a++)
        #pragma unroll
        for (int b = 0; b < 8; b++)
            #pragma unroll
            for (int c = 0; c < 4; c++) acc[a][b][c] = 0.f;

    int aseg = tid & 7;
    int arr  = tid >> 3;                // 0..63
    int ap0  = p0 + arr, ap1 = ap0 + 64;
    int ah0  = ap0 / IW, aw0 = ap0 % IW;
    int ah1  = ap1 / IW, aw1 = ap1 % IW;

    auto load_chunk = [&](int k, int stage) {
        uint32_t sa = smem_base + OFF_A0 + stage * STAGE_BYTES;
        uint32_t sb = sa + A_BYTES;
        int tap = k / KCH, kc = k % KCH;
        int dy = (taps == 9) ? (tap / 3 - 1) : 0;
        int dx = (taps == 9) ? (tap % 3 - 1) : 0;
        int cbase = kc * 64;
        {
            int h2 = ah0 + dy, w2 = aw0 + dx;
            bool ok = (ap0 < HWPX) && (h2 >= 0) && (h2 < IH) && (w2 >= 0) && (w2 < IW);
            const __half* gp = ok
                ? (abase + (size_t)(h2 * IW + w2) * 256 + cbase + aseg * 8)
                : abase;
            cp_async16(sa + arr * RSTRIDE + aseg * 16, gp, ok ? 16 : 0);
        }
        {
            int h2 = ah1 + dy, w2 = aw1 + dx;
            bool ok = (ap1 < HWPX) && (h2 >= 0) && (h2 < IH) && (w2 >= 0) && (w2 < IW);
            const __half* gp = ok
                ? (abase + (size_t)(h2 * IW + w2) * 256 + cbase + aseg * 8)
                : abase;
            cp_async16(sa + (arr + 64) * RSTRIDE + aseg * 16, gp, ok ? 16 : 0);
        }
        const __half* wb = wp + (size_t)k * (256 * 64);
        #pragma unroll
        for (int i = 0; i < 4; i++) {
            int idx = tid + i * 512;
            int r = idx >> 3, seg = idx & 7;
            cp_async16(sb + r * RSTRIDE + seg * 16, wb + r * 64 + seg * 8, 16);
        }
        cp_commit();
    };

    auto compute_chunk = [&](int k) {
        uint32_t sa = smem_base + OFF_A0 + (k & 3) * STAGE_BYTES;
        uint32_t sb = sa + A_BYTES;
        uint32_t a_row = m0 + (lane & 15);
        uint32_t a_coloff = (lane >> 4) * 16;
        uint32_t b_row = n0 + (lane >> 4) * 8 + (lane & 7);
        uint32_t b_coloff = ((lane >> 3) & 1) * 16;

        #pragma unroll
        for (int kk = 0; kk < 4; kk++) {
            uint32_t af[2][4];
            #pragma unroll
            for (int mf = 0; mf < 2; mf++) {
                uint32_t addr = sa + (a_row + mf * 16) * RSTRIDE + kk * 32 + a_coloff;
                ldmx4(addr, af[mf][0], af[mf][1], af[mf][2], af[mf][3]);
            }
            uint32_t bf[4][4];
            #pragma unroll
            for (int nf2 = 0; nf2 < 4; nf2++) {
                uint32_t addr = sb + (b_row + nf2 * 16) * RSTRIDE + kk * 32 + b_coloff;
                ldmx4(addr, bf[nf2][0], bf[nf2][1], bf[nf2][2], bf[nf2][3]);
            }
            #pragma unroll
            for (int mf = 0; mf < 2; mf++)
                #pragma unroll
                for (int nf = 0; nf < 8; nf++)
                    mma16816(acc[mf][nf], af[mf], bf[nf >> 1][(nf & 1) * 2], bf[nf >> 1][(nf & 1) * 2 + 1]);
        }
    };

    load_chunk(0, 0);
    load_chunk(1, 1);

    for (int k = 0; k < nch; k += 2) {
        cp_wait0();
        __syncthreads();
        if (k + 2 < nch) { load_chunk(k + 2, (k + 2) & 3); load_chunk(k + 3, (k + 3) & 3); }
        compute_chunk(k);
        compute_chunk(k + 1);
    }

    const float* s_ss = (const float*)smem;
    int trow = lane >> 2;
    int tc   = (lane & 3) * 2;

    #pragma unroll
    for (int mf = 0; mf < 2; mf++) {
        #pragma unroll
        for (int hf = 0; hf < 2; hf++) {
            int pr = m0 + mf * 16 + hf * 8 + trow;
            int p = p0 + pr;
            if (p >= HWPX) continue;
            size_t pxg = (size_t)cam * HWPX + p;
            #pragma unroll
            for (int nf = 0; nf < 8; nf++) {
                int co = n0 + nf * 8 + tc;
                float d0 = acc[mf][nf][hf * 2];
                float d1 = acc[mf][nf][hf * 2 + 1];
                if (mode == 0) {
                    float y0 = fmaxf(d0 * s_ss[co]     + s_ss[256 + co],     0.f);
                    float y1 = fmaxf(d1 * s_ss[co + 1] + s_ss[256 + co + 1], 0.f);
                    *(__half2*)(act_out + pxg * 256 + co) =
                        __halves2half2(__float2half_rn(y0), __float2half_rn(y1));
                } else {
                    float2 v = make_float2(d0 + s_ss[co], d1 + s_ss[co + 1]);
                    *(float2*)(logits_out + pxg * 256 + co) = v;
                }
            }
        }
    }
}

// ---------------- fused mega-prep: weights | convert | small | scratch-zero ----------------
#define W3X3_ELEMS (9*4*256*64)
#define W1X1_ELEMS (4*256*64)
#define WTOTAL     (2*W3X3_ELEMS + W1X1_ELEMS)
#define WBLOCKS    (WTOTAL/256)
#define CVX        ((HWPX+63)/64)
#define CVBLOCKS   (CVX*4*NCAM)
#define ZTOTAL     (NZV*NXY*CC)
#define ZPERBLK    (256*16)
#define ZBLOCKS    ((ZTOTAL+ZPERBLK-1)/ZPERBLK)
#define MEGA_BLOCKS (WBLOCKS + CVBLOCKS + 1 + ZBLOCKS)

__device__ void inv3(const float* a, float* o) {
    float det = a[0]*(a[4]*a[8]-a[5]*a[7]) - a[1]*(a[3]*a[8]-a[5]*a[6]) + a[2]*(a[3]*a[7]-a[4]*a[6]);
    float id = 1.0f/det;
    o[0]=(a[4]*a[8]-a[5]*a[7])*id; o[1]=(a[2]*a[7]-a[1]*a[8])*id; o[2]=(a[1]*a[5]-a[2]*a[4])*id;
    o[3]=(a[5]*a[6]-a[3]*a[8])*id; o[4]=(a[0]*a[8]-a[2]*a[6])*id; o[5]=(a[2]*a[3]-a[0]*a[5])*id;
    o[6]=(a[3]*a[7]-a[4]*a[6])*id; o[7]=(a[1]*a[6]-a[0]*a[7])*id; o[8]=(a[0]*a[4]-a[1]*a[3])*id;
}

__global__ __launch_bounds__(256)
void mega_prep(const float* __restrict__ w1, const float* __restrict__ w2,
               const float* __restrict__ w3,
               __half* __restrict__ wp1, __half* __restrict__ wp2, __half* __restrict__ wp3,
               const float* __restrict__ img, __half* __restrict__ actA,
               const float* b1, const float* g1, const float* be1, const float* m1, const float* v1,
               const float* b2, const float* g2, const float* be2, const float* m2, const float* v2,
               const float* b3,
               const float* rot, const float* ctrans, const float* intr,
               const float* prot, const float* ptrans,
               float* __restrict__ scratch)
{
    __shared__ float s[64][65];
    int bx = blockIdx.x;
    int tid = threadIdx.x;

    if (bx < WBLOCKS) {
        int idx = bx * 256 + tid;
        if (idx < 2 * W3X3_ELEMS) {
            const float* w = (idx < W3X3_ELEMS) ? w1 : w2;
            __half* wp = (idx < W3X3_ELEMS) ? wp1 : wp2;
            int e = (idx < W3X3_ELEMS) ? idx : idx - W3X3_ELEMS;
            int j   = e & 63;
            int co  = (e >> 6) & 255;
            int kc  = (e >> 14) & 3;
            int tap = e >> 16;
            int ci = kc * 64 + j;
            int ky = tap / 3, kx = tap % 3;
            wp[e] = __float2half_rn(w[(((size_t)co * 256 + ci) * 3 + ky) * 3 + kx]);
        } else {
            int e = idx - 2 * W3X3_ELEMS;
            int j  = e & 63;
            int co = (e >> 6) & 255;
            int kc = e >> 14;
            int ci = kc * 64 + j;
            float v = (co < 227) ? w3[(size_t)co * 256 + ci] : 0.f;
            wp3[e] = __float2half_rn(v);
        }
        return;
    }
    bx -= WBLOCKS;

    if (bx < CVBLOCKS) {
        int x = bx % CVX;
        int y = (bx / CVX) & 3;
        int n = bx / (CVX * 4);
        int ci0 = y * 64;
        int p0 = x * 64;
        for (int idx = tid; idx < 64 * 64; idx += 256) {
            int ci = idx / 64, p = idx % 64;
            float v = 0.f;
            if (p0 + p < HWPX) v = img[((size_t)(n * FCH + ci0 + ci)) * HWPX + p0 + p];
            s[ci][p] = v;
        }
        __syncthreads();
        for (int idx = tid; idx < 64 * 64; idx += 256) {
            int p = idx / 64, ci = idx % 64;
            if (p0 + p >= HWPX) continue;
            actA[((size_t)n * HWPX + p0 + p) * 256 + ci0 + ci] = __float2half_rn(s[ci][p]);
        }
        return;
    }
    bx -= CVBLOCKS;

    if (bx == 0) {
        int c = tid;
        float s1 = g1[c] * rsqrtf(v1[c] + 1e-3f);
        g_ss[c] = s1;
        g_ss[256 + c] = be1[c] + (b1[c] - m1[c]) * s1;
        float s2 = g2[c] * rsqrtf(v2[c] + 1e-3f);
        g_ss[512 + c] = s2;
        g_ss[768 + c] = be2[c] + (b2[c] - m2[c]) * s2;
        g_ss[1024 + c] = (c < 227) ? b3[c] : 0.f;
        if (c < NCAM) {
            int n = c;
            float invK[9], invPR[9];
            inv3(intr + n*9, invK);
            inv3(prot + n*9, invPR);
            const float* R = rot + n*9;
            float* m = g_mats[n];
            #pragma unroll
            for (int i=0;i<3;i++)
                #pragma unroll
                for (int j=0;j<3;j++){
                    float acc2=0.f;
                    #pragma unroll
                    for (int k2=0;k2<3;k2++) acc2 += R[i*3+k2]*invK[k2*3+j];
                    m[i*3+j]=acc2;
                }
            #pragma unroll
            for (int i=0;i<9;i++) m[9+i]=invPR[i];
            #pragma unroll
            for (int i=0;i<3;i++){ m[18+i]=ptrans[n*3+i]; m[21+i]=ctrans[n*3+i]; }
        }
        return;
    }
    bx -= 1;

    {
        size_t base = (size_t)bx * ZPERBLK + (size_t)tid * 16;
        float4 z = make_float4(0.f, 0.f, 0.f, 0.f);
        #pragma unroll
        for (int i = 0; i < 4; i++) {
            size_t off = base + i * 4;
            if (off < ZTOTAL) *(float4*)(scratch + off) = z;
        }
    }
}

// ---------------- fused softmax + geometry + quad-merged scatter (R13 version) ----------------
#define MAXE (4*DD)   // 396
__global__ __launch_bounds__(128)
void scatter_kernel(const float* __restrict__ logits, float* __restrict__ scratch)
{
    __shared__ float s_m[24];
    __shared__ float s_p[4][DD];
    __shared__ int   s_vox[4][DD];
    __shared__ __align__(16) float s_ctx[4][CC];
    __shared__ int   s_evox[MAXE];
    __shared__ int   s_eray[MAXE];
    __shared__ float s_ew[MAXE];
    __shared__ float s_lw[MAXE*4];
    __shared__ int   s_lead[MAXE];
    __shared__ int   s_n;

    int blk = blockIdx.x;
    int n   = blk / (HWPX/4);
    int q   = blk % (HWPX/4);
    int h   = q / (IW/4);
    int w0  = (q % (IW/4)) * 4;
    int t = threadIdx.x, lane = t & 31, warp = t >> 5;

    if (t < 24) s_m[t] = g_mats[n][t];
    if (t == 0) s_n = 0;
    const float* lgbase = logits + ((size_t)n * HWPX + h * IW + w0) * 256;
    #pragma unroll
    for (int r = 0; r < 4; r++)
        s_ctx[r][t] = lgbase[r * 256 + DD + t];
    __syncthreads();

    {
        int r = warp;
        const float* lg = lgbase + r * 256;
        float xv[4];
        float lmax = -1e30f;
        #pragma unroll
        for (int j = 0; j < 4; j++) {
            int d = lane + 32 * j;
            xv[j] = (d < DD) ? lg[d] : -1e30f;
            lmax = fmaxf(lmax, xv[j]);
        }
        #pragma unroll
        for (int o = 16; o; o >>= 1) lmax = fmaxf(lmax, __shfl_xor_sync(0xffffffffu, lmax, o));
        float ev[4], lsum = 0.f;
        #pragma unroll
        for (int j = 0; j < 4; j++) {
            int d = lane + 32 * j;
            ev[j] = (d < DD) ? __expf(xv[j] - lmax) : 0.f;
            lsum += ev[j];
        }
        #pragma unroll
        for (int o = 16; o; o >>= 1) lsum += __shfl_xor_sync(0xffffffffu, lsum, o);
        float inv = 1.f / lsum;

        float fx = (w0 + r) * (639.0f / 79.0f);
        float fy = h * (359.0f / 44.0f);
        #pragma unroll
        for (int j = 0; j < 4; j++) {
            int d = lane + 32 * j;
            if (d >= DD) continue;
            s_p[r][d] = ev[j] * inv;
            float dv = (float)(d + 1);
            float q0 = fx - s_m[18], q1 = fy - s_m[19], q2 = dv - s_m[20];
            float r0 = s_m[ 9]*q0 + s_m[10]*q1 + s_m[11]*q2;
            float r1 = s_m[12]*q0 + s_m[13]*q1 + s_m[14]*q2;
            float r2 = s_m[15]*q0 + s_m[16]*q1 + s_m[17]*q2;
            float t0 = r0*r2, t1 = r1*r2, t2 = r2;
            float gx = s_m[0]*t0 + s_m[1]*t1 + s_m[2]*t2 + s_m[21];
            float gy = s_m[3]*t0 + s_m[4]*t1 + s_m[5]*t2 + s_m[22];
            float gz = s_m[6]*t0 + s_m[7]*t1 + s_m[8]*t2 + s_m[23];
            int vx = (int)floorf(gx * 0.5f);
            int vy = (int)floorf((gy + 100.f) * 0.5f);
            int vz = (int)floorf((gz + 10.f) * 0.25f);
            bool kept = (vx>=0 && vx<NXV && vy>=0 && vy<NYV && vz>=0 && vz<NZV);
            s_vox[r][d] = kept ? (vz*NXY + vx*NYV + vy) : -1;
        }
        __syncwarp();
        #pragma unroll
        for (int j = 0; j < 4; j++) {
            int d = lane + 32 * j;
            if (d >= DD) continue;
            int v = s_vox[r][d];
            if (v < 0) continue;
            bool f = (d == 0) || (s_vox[r][d-1] != v);
            if (!f) continue;
            float wsum = s_p[r][d];
            int dd = d + 1;
            while (dd < DD && s_vox[r][dd] == v) { wsum += s_p[r][dd]; dd++; }
            int idx = atomicAdd(&s_n, 1);
            s_evox[idx] = v;
            s_eray[idx] = r;
            s_ew[idx]   = wsum;
        }
    }
    __syncthreads();

    int N = s_n;
    for (int i = t; i < N * 4; i += 128) s_lw[i] = 0.f;
    __syncthreads();

    for (int i = t; i < N; i += 128) {
        int v = s_evox[i];
        int first = i;
        for (int j = 0; j < i; j++)
            if (s_evox[j] == v) { first = j; break; }
        s_lead[i] = (first == i) ? 1 : 0;
        atomicAdd(&s_lw[first * 4 + s_eray[i]], s_ew[i]);
    }
    __syncthreads();

    float4 c0 = ((const float4*)s_ctx[0])[lane];
    float4 c1 = ((const float4*)s_ctx[1])[lane];
    float4 c2 = ((const float4*)s_ctx[2])[lane];
    float4 c3 = ((const float4*)s_ctx[3])[lane];
    for (int e = warp; e < N; e += 4) {
        if (!s_lead[e]) continue;
        float a0 = s_lw[e*4], a1 = s_lw[e*4+1], a2 = s_lw[e*4+2], a3 = s_lw[e*4+3];
        float vx = a0*c0.x + a1*c1.x + a2*c2.x + a3*c3.x;
        float vy = a0*c0.y + a1*c1.y + a2*c2.y + a3*c3.y;
        float vz = a0*c0.z + a1*c1.z + a2*c2.z + a3*c3.z;
        float vw = a0*c0.w + a1*c1.w + a2*c2.w + a3*c3.w;
        float* ptr = scratch + (size_t)s_evox[e] * CC + lane * 4;
        asm volatile("red.global.add.v4.f32 [%0], {%1,%2,%3,%4};"
                     :: "l"(ptr), "f"(vx), "f"(vy), "f"(vz), "f"(vw)
                     : "memory");
    }
}

// ---------------- scratch [vz][xy][c] -> out [vz][c][xy] ----------------
__global__ __launch_bounds__(256)
void bev_transpose(const float* __restrict__ scratch, float* __restrict__ out)
{
    __shared__ float s[32][129];
    int vz = blockIdx.y;
    int xy0 = blockIdx.x * 32;
    int tid = threadIdx.x;
    #pragma unroll
    for (int i = 0; i < 16; i++) {
        int idx = tid + i * 256;
        int c = idx & 127, xyl = idx >> 7;
        int xy = xy0 + xyl;
        s[xyl][c] = (xy < NXY) ? scratch[((size_t)vz * NXY + xy) * CC + c] : 0.f;
    }
    __syncthreads();
    #pragma unroll
    for (int i = 0; i < 16; i++) {
        int idx = tid + i * 256;
        int xyl = idx & 31, c = idx >> 5;
        int xy = xy0 + xyl;
        if (xy < NXY) out[((size_t)vz * CC + c) * NXY + xy] = s[xyl][c];
    }
}

// ---------------- launcher ----------------
extern "C" void kernel_launch(void* const* d_in, const int* in_sizes, int n_in,
                              void* d_out, int out_size)
{
    const float* rot    = (const float*)d_in[0];
    const float* ctrans = (const float*)d_in[1];
    const float* intr   = (const float*)d_in[2];
    const float* prot   = (const float*)d_in[3];
    const float* ptrans = (const float*)d_in[4];
    const float* img    = (const float*)d_in[5];
    const float* w1 = (const float*)d_in[6];
    const float* b1 = (const float*)d_in[7];
    const float* g1 = (const float*)d_in[8];
    const float* be1= (const float*)d_in[9];
    const float* m1 = (const float*)d_in[10];
    const float* v1 = (const float*)d_in[11];
    const float* w2 = (const float*)d_in[12];
    const float* b2 = (const float*)d_in[13];
    const float* g2 = (const float*)d_in[14];
    const float* be2= (const float*)d_in[15];
    const float* m2 = (const float*)d_in[16];
    const float* v2 = (const float*)d_in[17];
    const float* w3 = (const float*)d_in[18];
    const float* b3 = (const float*)d_in[19];
    float* out = (float*)d_out;

    __half *actA, *actB, *wp1, *wp2, *wp3;
    float *logits, *ss, *scratch;
    cudaGetSymbolAddress((void**)&actA, g_actA);
    cudaGetSymbolAddress((void**)&actB, g_actB);
    cudaGetSymbolAddress((void**)&wp1, g_wp1);
    cudaGetSymbolAddress((void**)&wp2, g_wp2);
    cudaGetSymbolAddress((void**)&wp3, g_wp3);
    cudaGetSymbolAddress((void**)&logits, g_logits);
    cudaGetSymbolAddress((void**)&ss, g_ss);
    cudaGetSymbolAddress((void**)&scratch, g_scratch);

    cudaFuncSetAttribute(gemm_conv, cudaFuncAttributeMaxDynamicSharedMemorySize, SMEM_TOTAL);

    mega_prep<<<MEGA_BLOCKS, 256>>>(w1, w2, w3, wp1, wp2, wp3,
                                    img, actA,
                                    b1,g1,be1,m1,v1, b2,g2,be2,m2,v2, b3,
                                    rot, ctrans, intr, prot, ptrans,
                                    scratch);

    gemm_conv<<<NTILES, 512, SMEM_TOTAL>>>(actA, wp1, ss,        ss + 256, actB, nullptr, 9, 0);
    gemm_conv<<<NTILES, 512, SMEM_TOTAL>>>(actB, wp2, ss + 512,  ss + 768, actA, nullptr, 9, 0);
    gemm_conv<<<NTILES, 512, SMEM_TOTAL>>>(actA, wp3, ss + 1024, nullptr,  nullptr, logits, 1, 1);

    scatter_kernel<<<NPX/4, 128>>>(logits, scratch);

    bev_transpose<<<dim3((NXY + 31)/32, NZV), 256>>>(scratch, out);
}

// round 16
// speedup vs baseline: 1.3201x; 1.0933x over previous
#include <cuda_runtime.h>
#include <cuda_fp16.h>
#include <cstdint>
#include <math.h>

#define NCAM 4
#define FCH 256
#define IH 45
#define IW 80
#define HWPX (IH*IW)            // 3600
#define NPX (NCAM*HWPX)         // 14400
#define DD 99
#define CC 128
#define NXV 100
#define NYV 100
#define NZV 5
#define NXY (NXV*NYV)

#define TILES_PER_CAM 29        // ceil(3600/128)
#define NTILES (TILES_PER_CAM*NCAM)
#define KCH 4                   // 256/64 A-chunks per tap (pure fp16)

// ---------------- scratch ----------------
__device__ __half g_actA[(size_t)NPX*256];   // [px][256] fp16
__device__ __half g_actB[(size_t)NPX*256];
__device__ __half g_wp1[9*4*256*64];
__device__ __half g_wp2[9*4*256*64];
__device__ __half g_wp3[4*256*64];
__device__ float g_logits[(size_t)NPX*256];  // [px][227 used]
__device__ float g_ss[1280];
__device__ float g_mats[NCAM][24];
__device__ __align__(16) float g_scratch[(size_t)NZV*NXY*CC];  // [vz][xy][c]

// ---------------- helpers ----------------
__device__ __forceinline__ uint32_t smem_to_u32(const void* p) {
    uint32_t a;
    asm("{ .reg .u64 t; cvta.to.shared.u64 t, %1; cvt.u32.u64 %0, t; }" : "=r"(a) : "l"(p));
    return a;
}
__device__ __forceinline__ void cp_async16(uint32_t dst, const void* src, int sz) {
    asm volatile("cp.async.cg.shared.global [%0], [%1], 16, %2;"
                 :: "r"(dst), "l"(src), "r"(sz) : "memory");
}
__device__ __forceinline__ void cp_commit() { asm volatile("cp.async.commit_group;" ::: "memory"); }
__device__ __forceinline__ void cp_wait0()  { asm volatile("cp.async.wait_group 0;" ::: "memory"); }

__device__ __forceinline__ void ldmx4(uint32_t addr, uint32_t& r0, uint32_t& r1, uint32_t& r2, uint32_t& r3) {
    asm volatile("ldmatrix.sync.aligned.m8n8.x4.shared.b16 {%0,%1,%2,%3}, [%4];"
                 : "=r"(r0), "=r"(r1), "=r"(r2), "=r"(r3) : "r"(addr));
}
__device__ __forceinline__ void mma16816(float* d, const uint32_t* a, uint32_t b0, uint32_t b1) {
    asm volatile("mma.sync.aligned.m16n8k16.row.col.f32.f16.f16.f32 "
                 "{%0,%1,%2,%3}, {%4,%5,%6,%7}, {%8,%9}, {%0,%1,%2,%3};"
                 : "+f"(d[0]), "+f"(d[1]), "+f"(d[2]), "+f"(d[3])
                 : "r"(a[0]), "r"(a[1]), "r"(a[2]), "r"(a[3]), "r"(b0), "r"(b1));
}

// ---------------- smem layout: 128px x 256co tile, 4-stage ----------------
#define RSTRIDE 144
#define OFF_SS   0
#define OFF_A0   2048
#define A_BYTES  (128*RSTRIDE)          // 18432
#define B_BYTES  (256*RSTRIDE)          // 36864
#define STAGE_BYTES (A_BYTES + B_BYTES) // 55296
#define SMEM_TOTAL (OFF_A0 + 4*STAGE_BYTES)  // 223232

// ---------------- GEMM conv kernel (mma.sync fp16, fp32 accum) ----------------
__global__ __launch_bounds__(512, 1)
void gemm_conv(const __half* __restrict__ act_in,
               const __half* __restrict__ wp,
               const float* __restrict__ ssA, const float* __restrict__ ssB,
               __half* __restrict__ act_out,
               float* __restrict__ logits_out,
               int taps, int mode)
{
    extern __shared__ char smem[];
    uint32_t smem_base = smem_to_u32(smem);
    int tid = threadIdx.x;
    int wid = tid >> 5;
    int lane = tid & 31;

    int tile = blockIdx.x;
    int cam = tile / TILES_PER_CAM;
    int p0  = (tile % TILES_PER_CAM) * 128;

    {
        float* s_ss = (float*)smem;
        if (tid < 256) s_ss[tid] = ssA[tid];
        else           s_ss[tid] = ssB ? ssB[tid - 256] : 0.f;
    }

    const __half* abase = act_in + (size_t)cam * HWPX * 256;
    int nch = taps * KCH;

    int warp_m = wid >> 2, warp_n = wid & 3;
    int m0 = warp_m * 32;
    int n0 = warp_n * 64;

    float acc[2][8][4];
    #pragma unroll
    for (int a = 0; a < 2; a++)
        #pragma unroll
        for (int b = 0; b < 8; b++)
            #pragma unroll
            for (int c = 0; c < 4; c++) acc[a][b][c] = 0.f;

    int aseg = tid & 7;
    int arr  = tid >> 3;
    int ap0  = p0 + arr, ap1 = ap0 + 64;
    int ah0  = ap0 / IW, aw0 = ap0 % IW;
    int ah1  = ap1 / IW, aw1 = ap1 % IW;

    auto load_chunk = [&](int k, int stage) {
        uint32_t sa = smem_base + OFF_A0 + stage * STAGE_BYTES;
        uint32_t sb = sa + A_BYTES;
        int tap = k / KCH, kc = k % KCH;
        int dy = (taps == 9) ? (tap / 3 - 1) : 0;
        int dx = (taps == 9) ? (tap % 3 - 1) : 0;
        int cbase = kc * 64;
        {
            int h2 = ah0 + dy, w2 = aw0 + dx;
            bool ok = (ap0 < HWPX) && (h2 >= 0) && (h2 < IH) && (w2 >= 0) && (w2 < IW);
            const __half* gp = ok
                ? (abase + (size_t)(h2 * IW + w2) * 256 + cbase + aseg * 8)
                : abase;
            cp_async16(sa + arr * RSTRIDE + aseg * 16, gp, ok ? 16 : 0);
        }
        {
            int h2 = ah1 + dy, w2 = aw1 + dx;
            bool ok = (ap1 < HWPX) && (h2 >= 0) && (h2 < IH) && (w2 >= 0) && (w2 < IW);
            const __half* gp = ok
                ? (abase + (size_t)(h2 * IW + w2) * 256 + cbase + aseg * 8)
                : abase;
            cp_async16(sa + (arr + 64) * RSTRIDE + aseg * 16, gp, ok ? 16 : 0);
        }
        const __half* wb = wp + (size_t)k * (256 * 64);
        #pragma unroll
        for (int i = 0; i < 4; i++) {
            int idx = tid + i * 512;
            int r = idx >> 3, seg = idx & 7;
            cp_async16(sb + r * RSTRIDE + seg * 16, wb + r * 64 + seg * 8, 16);
        }
        cp_commit();
    };

    auto compute_chunk = [&](int k) {
        uint32_t sa = smem_base + OFF_A0 + (k & 3) * STAGE_BYTES;
        uint32_t sb = sa + A_BYTES;
        uint32_t a_row = m0 + (lane & 15);
        uint32_t a_coloff = (lane >> 4) * 16;
        uint32_t b_row = n0 + (lane >> 4) * 8 + (lane & 7);
        uint32_t b_coloff = ((lane >> 3) & 1) * 16;

        #pragma unroll
        for (int kk = 0; kk < 4; kk++) {
            uint32_t af[2][4];
            #pragma unroll
            for (int mf = 0; mf < 2; mf++) {
                uint32_t addr = sa + (a_row + mf * 16) * RSTRIDE + kk * 32 + a_coloff;
                ldmx4(addr, af[mf][0], af[mf][1], af[mf][2], af[mf][3]);
            }
            uint32_t bf[4][4];
            #pragma unroll
            for (int nf2 = 0; nf2 < 4; nf2++) {
                uint32_t addr = sb + (b_row + nf2 * 16) * RSTRIDE + kk * 32 + b_coloff;
                ldmx4(addr, bf[nf2][0], bf[nf2][1], bf[nf2][2], bf[nf2][3]);
            }
            #pragma unroll
            for (int mf = 0; mf < 2; mf++)
                #pragma unroll
                for (int nf = 0; nf < 8; nf++)
                    mma16816(acc[mf][nf], af[mf], bf[nf >> 1][(nf & 1) * 2], bf[nf >> 1][(nf & 1) * 2 + 1]);
        }
    };

    load_chunk(0, 0);
    load_chunk(1, 1);

    for (int k = 0; k < nch; k += 2) {
        cp_wait0();
        __syncthreads();
        if (k + 2 < nch) { load_chunk(k + 2, (k + 2) & 3); load_chunk(k + 3, (k + 3) & 3); }
        compute_chunk(k);
        compute_chunk(k + 1);
    }

    const float* s_ss = (const float*)smem;
    int trow = lane >> 2;
    int tc   = (lane & 3) * 2;

    #pragma unroll
    for (int mf = 0; mf < 2; mf++) {
        #pragma unroll
        for (int hf = 0; hf < 2; hf++) {
            int pr = m0 + mf * 16 + hf * 8 + trow;
            int p = p0 + pr;
            if (p >= HWPX) continue;
            size_t pxg = (size_t)cam * HWPX + p;
            #pragma unroll
            for (int nf = 0; nf < 8; nf++) {
                int co = n0 + nf * 8 + tc;
                float d0 = acc[mf][nf][hf * 2];
                float d1 = acc[mf][nf][hf * 2 + 1];
                if (mode == 0) {
                    float y0 = fmaxf(d0 * s_ss[co]     + s_ss[256 + co],     0.f);
                    float y1 = fmaxf(d1 * s_ss[co + 1] + s_ss[256 + co + 1], 0.f);
                    *(__half2*)(act_out + pxg * 256 + co) =
                        __halves2half2(__float2half_rn(y0), __float2half_rn(y1));
                } else {
                    float2 v = make_float2(d0 + s_ss[co], d1 + s_ss[co + 1]);
                    *(float2*)(logits_out + pxg * 256 + co) = v;
                }
            }
        }
    }
}

// ---------------- fused mega-prep ----------------
#define W3X3_ELEMS (9*4*256*64)
#define W1X1_ELEMS (4*256*64)
#define WTOTAL     (2*W3X3_ELEMS + W1X1_ELEMS)
#define WBLOCKS    (WTOTAL/256)
#define CVX        ((HWPX+63)/64)
#define CVBLOCKS   (CVX*4*NCAM)
#define ZTOTAL     (NZV*NXY*CC)
#define ZPERBLK    (256*16)
#define ZBLOCKS    ((ZTOTAL+ZPERBLK-1)/ZPERBLK)
#define MEGA_BLOCKS (WBLOCKS + CVBLOCKS + 1 + ZBLOCKS)

__device__ void inv3(const float* a, float* o) {
    float det = a[0]*(a[4]*a[8]-a[5]*a[7]) - a[1]*(a[3]*a[8]-a[5]*a[6]) + a[2]*(a[3]*a[7]-a[4]*a[6]);
    float id = 1.0f/det;
    o[0]=(a[4]*a[8]-a[5]*a[7])*id; o[1]=(a[2]*a[7]-a[1]*a[8])*id; o[2]=(a[1]*a[5]-a[2]*a[4])*id;
    o[3]=(a[5]*a[6]-a[3]*a[8])*id; o[4]=(a[0]*a[8]-a[2]*a[6])*id; o[5]=(a[2]*a[3]-a[0]*a[5])*id;
    o[6]=(a[3]*a[7]-a[4]*a[6])*id; o[7]=(a[1]*a[6]-a[0]*a[7])*id; o[8]=(a[0]*a[4]-a[1]*a[3])*id;
}

__global__ __launch_bounds__(256)
void mega_prep(const float* __restrict__ w1, const float* __restrict__ w2,
               const float* __restrict__ w3,
               __half* __restrict__ wp1, __half* __restrict__ wp2, __half* __restrict__ wp3,
               const float* __restrict__ img, __half* __restrict__ actA,
               const float* b1, const float* g1, const float* be1, const float* m1, const float* v1,
               const float* b2, const float* g2, const float* be2, const float* m2, const float* v2,
               const float* b3,
               const float* rot, const float* ctrans, const float* intr,
               const float* prot, const float* ptrans,
               float* __restrict__ scratch)
{
    __shared__ float s[64][65];
    int bx = blockIdx.x;
    int tid = threadIdx.x;

    if (bx < WBLOCKS) {
        int idx = bx * 256 + tid;
        if (idx < 2 * W3X3_ELEMS) {
            const float* w = (idx < W3X3_ELEMS) ? w1 : w2;
            __half* wp = (idx < W3X3_ELEMS) ? wp1 : wp2;
            int e = (idx < W3X3_ELEMS) ? idx : idx - W3X3_ELEMS;
            int j   = e & 63;
            int co  = (e >> 6) & 255;
            int kc  = (e >> 14) & 3;
            int tap = e >> 16;
            int ci = kc * 64 + j;
            int ky = tap / 3, kx = tap % 3;
            wp[e] = __float2half_rn(w[(((size_t)co * 256 + ci) * 3 + ky) * 3 + kx]);
        } else {
            int e = idx - 2 * W3X3_ELEMS;
            int j  = e & 63;
            int co = (e >> 6) & 255;
            int kc = e >> 14;
            int ci = kc * 64 + j;
            float v = (co < 227) ? w3[(size_t)co * 256 + ci] : 0.f;
            wp3[e] = __float2half_rn(v);
        }
        return;
    }
    bx -= WBLOCKS;

    if (bx < CVBLOCKS) {
        int x = bx % CVX;
        int y = (bx / CVX) & 3;
        int n = bx / (CVX * 4);
        int ci0 = y * 64;
        int p0 = x * 64;
        for (int idx = tid; idx < 64 * 64; idx += 256) {
            int ci = idx / 64, p = idx % 64;
            float v = 0.f;
            if (p0 + p < HWPX) v = img[((size_t)(n * FCH + ci0 + ci)) * HWPX + p0 + p];
            s[ci][p] = v;
        }
        __syncthreads();
        for (int idx = tid; idx < 64 * 64; idx += 256) {
            int p = idx / 64, ci = idx % 64;
            if (p0 + p >= HWPX) continue;
            actA[((size_t)n * HWPX + p0 + p) * 256 + ci0 + ci] = __float2half_rn(s[ci][p]);
        }
        return;
    }
    bx -= CVBLOCKS;

    if (bx == 0) {
        int c = tid;
        float s1 = g1[c] * rsqrtf(v1[c] + 1e-3f);
        g_ss[c] = s1;
        g_ss[256 + c] = be1[c] + (b1[c] - m1[c]) * s1;
        float s2 = g2[c] * rsqrtf(v2[c] + 1e-3f);
        g_ss[512 + c] = s2;
        g_ss[768 + c] = be2[c] + (b2[c] - m2[c]) * s2;
        g_ss[1024 + c] = (c < 227) ? b3[c] : 0.f;
        if (c < NCAM) {
            int n = c;
            float invK[9], invPR[9];
            inv3(intr + n*9, invK);
            inv3(prot + n*9, invPR);
            const float* R = rot + n*9;
            float* m = g_mats[n];
            #pragma unroll
            for (int i=0;i<3;i++)
                #pragma unroll
                for (int j=0;j<3;j++){
                    float acc2=0.f;
                    #pragma unroll
                    for (int k2=0;k2<3;k2++) acc2 += R[i*3+k2]*invK[k2*3+j];
                    m[i*3+j]=acc2;
                }
            #pragma unroll
            for (int i=0;i<9;i++) m[9+i]=invPR[i];
            #pragma unroll
            for (int i=0;i<3;i++){ m[18+i]=ptrans[n*3+i]; m[21+i]=ctrans[n*3+i]; }
        }
        return;
    }
    bx -= 1;

    {
        size_t base = (size_t)bx * ZPERBLK + (size_t)tid * 16;
        float4 z = make_float4(0.f, 0.f, 0.f, 0.f);
        #pragma unroll
        for (int i = 0; i < 4; i++) {
            size_t off = base + i * 4;
            if (off < ZTOTAL) *(float4*)(scratch + off) = z;
        }
    }
}

// ---------------- 8-ray scatter with O(N) hash dedup ----------------
#define RAYS 8
#define MAXE8 (RAYS*DD)                 // 792
#define HSZ 1024
// dynamic smem offsets (bytes)
#define SC_M    0                        // 96
#define SC_P    96                       // 3168
#define SC_VOX  3264                     // 3168
#define SC_CTX  6432                     // 4096 (16B aligned)
#define SC_HKEY 10528                    // 4096
#define SC_HIDX 14624                    // 4096
#define SC_EVOX 18720                    // 3168
#define SC_ERAY 21888                    // 3168
#define SC_EW   25056                    // 3168
#define SC_UVOX 28224                    // 3168
#define SC_LW   31392                    // 792*8*4 = 25344
#define SC_CNT  56736                    // 2 ints
#define SC_TOTAL 56744

__global__ __launch_bounds__(256)
void scatter_kernel(const float* __restrict__ logits, float* __restrict__ scratch)
{
    extern __shared__ char sm[];
    float* s_m    = (float*)(sm + SC_M);
    float* s_p    = (float*)(sm + SC_P);
    int*   s_vox  = (int*)  (sm + SC_VOX);
    float* s_ctx  = (float*)(sm + SC_CTX);
    int*   s_hkey = (int*)  (sm + SC_HKEY);
    int*   s_hidx = (int*)  (sm + SC_HIDX);
    int*   s_evox = (int*)  (sm + SC_EVOX);
    int*   s_eray = (int*)  (sm + SC_ERAY);
    float* s_ew   = (float*)(sm + SC_EW);
    int*   s_uvox = (int*)  (sm + SC_UVOX);
    float* s_lw   = (float*)(sm + SC_LW);
    int*   s_cnt  = (int*)  (sm + SC_CNT);   // [0]=entries, [1]=unique

    int blk = blockIdx.x;
    int n   = blk / (HWPX/RAYS);
    int q   = blk % (HWPX/RAYS);
    int h   = q / (IW/RAYS);
    int w0  = (q % (IW/RAYS)) * RAYS;
    int t = threadIdx.x, lane = t & 31, warp = t >> 5;

    if (t < 24) s_m[t] = g_mats[n][t];
    if (t < 2) s_cnt[t] = 0;
    for (int i = t; i < HSZ; i += 256) s_hkey[i] = -1;
    const float* lgbase = logits + ((size_t)n * HWPX + h * IW + w0) * 256;
    for (int i = t; i < RAYS * CC; i += 256) {
        int r = i >> 7, c = i & 127;
        s_ctx[i] = lgbase[r * 256 + DD + c];
    }
    __syncthreads();

    // ---- phase 1: per-warp softmax + geometry + run extraction ----
    {
        int r = warp;
        const float* lg = lgbase + r * 256;
        float xv[4];
        float lmax = -1e30f;
        #pragma unroll
        for (int j = 0; j < 4; j++) {
            int d = lane + 32 * j;
            xv[j] = (d < DD) ? lg[d] : -1e30f;
            lmax = fmaxf(lmax, xv[j]);
        }
        #pragma unroll
        for (int o = 16; o; o >>= 1) lmax = fmaxf(lmax, __shfl_xor_sync(0xffffffffu, lmax, o));
        float ev[4], lsum = 0.f;
        #pragma unroll
        for (int j = 0; j < 4; j++) {
            int d = lane + 32 * j;
            ev[j] = (d < DD) ? __expf(xv[j] - lmax) : 0.f;
            lsum += ev[j];
        }
        #pragma unroll
        for (int o = 16; o; o >>= 1) lsum += __shfl_xor_sync(0xffffffffu, lsum, o);
        float inv = 1.f / lsum;

        float fx = (w0 + r) * (639.0f / 79.0f);
        float fy = h * (359.0f / 44.0f);
        #pragma unroll
        for (int j = 0; j < 4; j++) {
            int d = lane + 32 * j;
            if (d >= DD) continue;
            s_p[r * DD + d] = ev[j] * inv;
            float dv = (float)(d + 1);
            float q0 = fx - s_m[18], q1 = fy - s_m[19], q2 = dv - s_m[20];
            float r0 = s_m[ 9]*q0 + s_m[10]*q1 + s_m[11]*q2;
            float r1 = s_m[12]*q0 + s_m[13]*q1 + s_m[14]*q2;
            float r2 = s_m[15]*q0 + s_m[16]*q1 + s_m[17]*q2;
            float t0 = r0*r2, t1 = r1*r2, t2 = r2;
            float gx = s_m[0]*t0 + s_m[1]*t1 + s_m[2]*t2 + s_m[21];
            float gy = s_m[3]*t0 + s_m[4]*t1 + s_m[5]*t2 + s_m[22];
            float gz = s_m[6]*t0 + s_m[7]*t1 + s_m[8]*t2 + s_m[23];
            int vx = (int)floorf(gx * 0.5f);
            int vy = (int)floorf((gy + 100.f) * 0.5f);
            int vz = (int)floorf((gz + 10.f) * 0.25f);
            bool kept = (vx>=0 && vx<NXV && vy>=0 && vy<NYV && vz>=0 && vz<NZV);
            s_vox[r * DD + d] = kept ? (vz*NXY + vx*NYV + vy) : -1;
        }
        __syncwarp();
        #pragma unroll
        for (int j = 0; j < 4; j++) {
            int d = lane + 32 * j;
            if (d >= DD) continue;
            int v = s_vox[r * DD + d];
            if (v < 0) continue;
            bool f = (d == 0) || (s_vox[r * DD + d - 1] != v);
            if (!f) continue;
            float wsum = s_p[r * DD + d];
            int dd = d + 1;
            while (dd < DD && s_vox[r * DD + dd] == v) { wsum += s_p[r * DD + dd]; dd++; }
            int idx = atomicAdd(&s_cnt[0], 1);
            s_evox[idx] = v;
            s_eray[idx] = r;
            s_ew[idx]   = wsum;
        }
    }
    __syncthreads();

    int N = s_cnt[0];

    // ---- phase 2a: hash-insert unique voxels ----
    for (int i = t; i < N; i += 256) {
        int v = s_evox[i];
        uint32_t hh = ((uint32_t)v * 2654435761u >> 16) & (HSZ - 1);
        while (true) {
            int old = atomicCAS(&s_hkey[hh], -1, v);
            if (old == -1) {
                int u = atomicAdd(&s_cnt[1], 1);
                s_hidx[hh] = u;
                s_uvox[u] = v;
                break;
            }
            if (old == v) break;
            hh = (hh + 1) & (HSZ - 1);
        }
    }
    __syncthreads();

    int NU = s_cnt[1];
    for (int i = t; i < NU * RAYS; i += 256) s_lw[i] = 0.f;
    __syncthreads();

    // ---- phase 2b: accumulate per-(voxel, ray) weights ----
    for (int i = t; i < N; i += 256) {
        int v = s_evox[i];
        uint32_t hh = ((uint32_t)v * 2654435761u >> 16) & (HSZ - 1);
        while (s_hkey[hh] != v) hh = (hh + 1) & (HSZ - 1);
        int u = s_hidx[hh];
        atomicAdd(&s_lw[u * RAYS + s_eray[i]], s_ew[i]);
    }
    __syncthreads();

    // ---- phase 3: flush compact unique list ----
    float4 cv[RAYS];
    #pragma unroll
    for (int r = 0; r < RAYS; r++)
        cv[r] = ((const float4*)(s_ctx + r * CC))[lane];
    for (int e = warp; e < NU; e += RAYS) {
        float vx = 0.f, vy = 0.f, vz = 0.f, vw = 0.f;
        #pragma unroll
        for (int r = 0; r < RAYS; r++) {
            float a = s_lw[e * RAYS + r];
            vx += a * cv[r].x; vy += a * cv[r].y;
            vz += a * cv[r].z; vw += a * cv[r].w;
        }
        float* ptr = scratch + (size_t)s_uvox[e] * CC + lane * 4;
        asm volatile("red.global.add.v4.f32 [%0], {%1,%2,%3,%4};"
                     :: "l"(ptr), "f"(vx), "f"(vy), "f"(vz), "f"(vw)
                     : "memory");
    }
}

// ---------------- scratch [vz][xy][c] -> out [vz][c][xy] ----------------
__global__ __launch_bounds__(256)
void bev_transpose(const float* __restrict__ scratch, float* __restrict__ out)
{
    __shared__ float s[32][129];
    int vz = blockIdx.y;
    int xy0 = blockIdx.x * 32;
    int tid = threadIdx.x;
    #pragma unroll
    for (int i = 0; i < 16; i++) {
        int idx = tid + i * 256;
        int c = idx & 127, xyl = idx >> 7;
        int xy = xy0 + xyl;
        s[xyl][c] = (xy < NXY) ? scratch[((size_t)vz * NXY + xy) * CC + c] : 0.f;
    }
    __syncthreads();
    #pragma unroll
    for (int i = 0; i < 16; i++) {
        int idx = tid + i * 256;
        int xyl = idx & 31, c = idx >> 5;
        int xy = xy0 + xyl;
        if (xy < NXY) out[((size_t)vz * CC + c) * NXY + xy] = s[xyl][c];
    }
}

// ---------------- launcher ----------------
extern "C" void kernel_launch(void* const* d_in, const int* in_sizes, int n_in,
                              void* d_out, int out_size)
{
    const float* rot    = (const float*)d_in[0];
    const float* ctrans = (const float*)d_in[1];
    const float* intr   = (const float*)d_in[2];
    const float* prot   = (const float*)d_in[3];
    const float* ptrans = (const float*)d_in[4];
    const float* img    = (const float*)d_in[5];
    const float* w1 = (const float*)d_in[6];
    const float* b1 = (const float*)d_in[7];
    const float* g1 = (const float*)d_in[8];
    const float* be1= (const float*)d_in[9];
    const float* m1 = (const float*)d_in[10];
    const float* v1 = (const float*)d_in[11];
    const float* w2 = (const float*)d_in[12];
    const float* b2 = (const float*)d_in[13];
    const float* g2 = (const float*)d_in[14];
    const float* be2= (const float*)d_in[15];
    const float* m2 = (const float*)d_in[16];
    const float* v2 = (const float*)d_in[17];
    const float* w3 = (const float*)d_in[18];
    const float* b3 = (const float*)d_in[19];
    float* out = (float*)d_out;

    __half *actA, *actB, *wp1, *wp2, *wp3;
    float *logits, *ss, *scratch;
    cudaGetSymbolAddress((void**)&actA, g_actA);
    cudaGetSymbolAddress((void**)&actB, g_actB);
    cudaGetSymbolAddress((void**)&wp1, g_wp1);
    cudaGetSymbolAddress((void**)&wp2, g_wp2);
    cudaGetSymbolAddress((void**)&wp3, g_wp3);
    cudaGetSymbolAddress((void**)&logits, g_logits);
    cudaGetSymbolAddress((void**)&ss, g_ss);
    cudaGetSymbolAddress((void**)&scratch, g_scratch);

    cudaFuncSetAttribute(gemm_conv, cudaFuncAttributeMaxDynamicSharedMemorySize, SMEM_TOTAL);
    cudaFuncSetAttribute(scatter_kernel, cudaFuncAttributeMaxDynamicSharedMemorySize, SC_TOTAL);

    mega_prep<<<MEGA_BLOCKS, 256>>>(w1, w2, w3, wp1, wp2, wp3,
                                    img, actA,
                                    b1,g1,be1,m1,v1, b2,g2,be2,m2,v2, b3,
                                    rot, ctrans, intr, prot, ptrans,
                                    scratch);

    gemm_conv<<<NTILES, 512, SMEM_TOTAL>>>(actA, wp1, ss,        ss + 256, actB, nullptr, 9, 0);
    gemm_conv<<<NTILES, 512, SMEM_TOTAL>>>(actB, wp2, ss + 512,  ss + 768, actA, nullptr, 9, 0);
    gemm_conv<<<NTILES, 512, SMEM_TOTAL>>>(actA, wp3, ss + 1024, nullptr,  nullptr, logits, 1, 1);

    scatter_kernel<<<NPX/RAYS, 256, SC_TOTAL>>>(logits, scratch);

    bev_transpose<<<dim3((NXY + 31)/32, NZV), 256>>>(scratch, out);
}